// round 10
// baseline (speedup 1.0000x reference)
#include <cuda_runtime.h>
#include <cstdint>

#define SEQ   8192
#define EMB   256
#define HID   512
#define G4    2048   // 4*HID

// ---------------- scratch (static device arrays; no allocation) -------------
__device__ float g_Xg[(size_t)SEQ * G4];             // 64 MB precomputed input gates
__device__ __align__(16) float2 g_hpair[2][HID];     // (value, tag) pairs, 2 rotating slots

// ---------------- init: seed slot0 with (h0, tag=0), stamp slot1 ------------
__global__ void init_kernel(const float* __restrict__ h0) {
    int i = blockIdx.x * blockDim.x + threadIdx.x;
    if (i < HID) {
        g_hpair[0][i] = make_float2(h0[i], 0.0f);
        g_hpair[1][i] = make_float2(0.0f, -1.0f);   // never matches any expected tag
    }
}

// ---------------- GEMM: Xg[t][r] = emb[x[t]] . W_ih[r] + b_ih[r] + b_hh[r] --
#define TT 32
#define TR 64
#define KC 64

__global__ void __launch_bounds__(256) gemm_kernel(
    const int* __restrict__ x, const float* __restrict__ emb,
    const float* __restrict__ W_ih, const float* __restrict__ b_ih,
    const float* __restrict__ b_hh)
{
    __shared__ float As[TT][KC + 1];   // [t][k], padded
    __shared__ float Bs[KC][TR];       // [k][r]

    const int t0 = blockIdx.x * TT;
    const int r0 = blockIdx.y * TR;
    const int tid = threadIdx.x;
    const int tx = tid & 15;    // r-quad index (r = r0 + tx*4 + q)
    const int ty = tid >> 4;    // t index (t = t0 + ty, t0 + ty + 16)

    float acc[2][4];
    #pragma unroll
    for (int i = 0; i < 2; i++)
        #pragma unroll
        for (int q = 0; q < 4; q++) acc[i][q] = 0.f;

    for (int kc = 0; kc < EMB; kc += KC) {
        #pragma unroll
        for (int i = 0; i < 2; i++) {
            int task = tid * 2 + i;        // 0..511
            int t    = task >> 4;          // 16 float4 per row
            int kq   = task & 15;
            int row  = x[t0 + t];
            float4 v = *reinterpret_cast<const float4*>(
                emb + (size_t)row * EMB + kc + kq * 4);
            As[t][kq * 4 + 0] = v.x;
            As[t][kq * 4 + 1] = v.y;
            As[t][kq * 4 + 2] = v.z;
            As[t][kq * 4 + 3] = v.w;
        }
        #pragma unroll
        for (int i = 0; i < 4; i++) {
            int task = tid * 4 + i;        // 0..1023
            int r    = task >> 4;          // 0..63
            int kq   = task & 15;
            float4 v = *reinterpret_cast<const float4*>(
                W_ih + (size_t)(r0 + r) * EMB + kc + kq * 4);
            Bs[kq * 4 + 0][r] = v.x;
            Bs[kq * 4 + 1][r] = v.y;
            Bs[kq * 4 + 2][r] = v.z;
            Bs[kq * 4 + 3][r] = v.w;
        }
        __syncthreads();

        #pragma unroll 8
        for (int k = 0; k < KC; k++) {
            float a0 = As[ty][k];
            float a1 = As[ty + 16][k];
            float4 b = *reinterpret_cast<const float4*>(&Bs[k][tx * 4]);
            acc[0][0] += a0 * b.x;  acc[0][1] += a0 * b.y;
            acc[0][2] += a0 * b.z;  acc[0][3] += a0 * b.w;
            acc[1][0] += a1 * b.x;  acc[1][1] += a1 * b.y;
            acc[1][2] += a1 * b.z;  acc[1][3] += a1 * b.w;
        }
        __syncthreads();
    }

    const int rbase = r0 + tx * 4;
    float4 bias;
    bias.x = b_ih[rbase + 0] + b_hh[rbase + 0];
    bias.y = b_ih[rbase + 1] + b_hh[rbase + 1];
    bias.z = b_ih[rbase + 2] + b_hh[rbase + 2];
    bias.w = b_ih[rbase + 3] + b_hh[rbase + 3];
    #pragma unroll
    for (int i = 0; i < 2; i++) {
        int t = t0 + ty + i * 16;
        float4 o;
        o.x = acc[i][0] + bias.x;
        o.y = acc[i][1] + bias.y;
        o.z = acc[i][2] + bias.z;
        o.w = acc[i][3] + bias.w;
        *reinterpret_cast<float4*>(g_Xg + (size_t)t * G4 + rbase) = o;
    }
}

// ---------------- recurrent LSTM: persistent, collective-agree synced --------
#define NCTA   64
#define NWARP  8      // warps per CTA; NCTA*NWARP == HID (one unit per warp)
#define NTHR   (NWARP * 32)

__device__ __forceinline__ float sigmoid_f(float x) {
    return __fdividef(1.f, 1.f + __expf(-x));
}
__device__ __forceinline__ float tanh_f(float x) {
    float e = __expf(2.f * x);
    return 1.f - __fdividef(2.f, e + 1.f);
}

__device__ __forceinline__ unsigned long long pack2(float lo, float hi) {
    unsigned long long r;
    asm("mov.b64 %0, {%1, %2};" : "=l"(r)
        : "r"(__float_as_uint(lo)), "r"(__float_as_uint(hi)));
    return r;
}
__device__ __forceinline__ void unpack2(unsigned long long v, float& lo, float& hi) {
    unsigned a, b;
    asm("mov.b64 {%0, %1}, %2;" : "=r"(a), "=r"(b) : "l"(v));
    lo = __uint_as_float(a); hi = __uint_as_float(b);
}
__device__ __forceinline__ void ffma2(unsigned long long& acc,
                                      unsigned long long a, unsigned long long b) {
    asm("fma.rn.f32x2 %0, %1, %2, %0;" : "+l"(acc) : "l"(a), "l"(b));
}

__global__ void __launch_bounds__(NTHR, 1) lstm_kernel(
    const float* __restrict__ W_hh, const float* __restrict__ c0,
    float* __restrict__ out)
{
    const int tid  = threadIdx.x;
    const int warp = tid >> 5;
    const int lane = tid & 31;
    const int j = blockIdx.x * NWARP + warp;     // hidden unit 0..511

    // single-buffer staging is safe here: the barrier INSIDE the poll loop
    // guarantees all warps finished step-t matvec reads before any thread can
    // pass the step-(t+1) poll and restage (this is the R3 invariant).
    __shared__ __align__(16) float hsm[HID];

    // --- preload 4 gate rows of W_hh, packed (gate0,gate1)/(gate2,gate3).
    // lane l owns k in { q*128 + l*4 + e : q=0..3, e=0..3 }  (matches hsm layout)
    unsigned long long w01[16], w23[16];
    {
        float wt[4][16];
        #pragma unroll
        for (int g = 0; g < 4; g++) {
            const float* row = W_hh + (size_t)(g * HID + j) * HID;
            #pragma unroll
            for (int q = 0; q < 4; q++) {
                float4 v = *reinterpret_cast<const float4*>(row + q * 128 + lane * 4);
                wt[g][q * 4 + 0] = v.x; wt[g][q * 4 + 1] = v.y;
                wt[g][q * 4 + 2] = v.z; wt[g][q * 4 + 3] = v.w;
            }
        }
        #pragma unroll
        for (int k = 0; k < 16; k++) {
            w01[k] = pack2(wt[0][k], wt[1][k]);
            w23[k] = pack2(wt[2][k], wt[3][k]);
        }
    }

    float c = c0[j];

    // prefetch Xg for t=0 (broadcast per warp)
    float xg0 = g_Xg[j +    0];
    float xg1 = g_Xg[j +  512];
    float xg2 = g_Xg[j + 1024];
    float xg3 = g_Xg[j + 1536];

    for (int t = 0; t < SEQ; t++) {
        // prefetch next step's Xg FIRST — latency hides under the poll
        int tn = (t + 1 < SEQ) ? (t + 1) : t;
        const float* xpn = g_Xg + (size_t)tn * G4 + j;
        float nx0 = xpn[0], nx1 = xpn[512], nx2 = xpn[1024], nx3 = xpn[1536];

        // ---- CTA-collective poll (R3 structure): one LDG.128 = 2 pairs/thread,
        // all 256 threads must agree via __syncthreads_and before anyone proceeds.
        const float4* src = reinterpret_cast<const float4*>(g_hpair[t & 1]);
        const int exp_bits = __float_as_int((float)t);
        float4 pa;
        int ok;
        do {
            pa = __ldcv(src + tid);            // pairs 2*tid, 2*tid+1
            ok = (__float_as_int(pa.y) == exp_bits) &
                 (__float_as_int(pa.w) == exp_bits);
        } while (!__syncthreads_and(ok));

        // stage values to smem (one 8B STS per thread), then visibility barrier
        *reinterpret_cast<float2*>(&hsm[tid * 2]) = make_float2(pa.x, pa.z);
        __syncthreads();

        // matvec slice: packed f32x2 — (gate0,gate1) and (gate2,gate3) pairs
        unsigned long long A01 = 0ull, A23 = 0ull;   // bit pattern (0.0f, 0.0f)
        #pragma unroll
        for (int q = 0; q < 4; q++) {
            float4 hq = *reinterpret_cast<const float4*>(&hsm[q * 128 + lane * 4]);
            float hv[4] = {hq.x, hq.y, hq.z, hq.w};
            #pragma unroll
            for (int e = 0; e < 4; e++) {
                unsigned long long hh = pack2(hv[e], hv[e]);
                ffma2(A01, w01[q * 4 + e], hh);
                ffma2(A23, w23[q * 4 + e], hh);
            }
        }
        float a0, a1, a2, a3;
        unpack2(A01, a0, a1);
        unpack2(A23, a2, a3);
        #pragma unroll
        for (int s = 16; s > 0; s >>= 1) {
            a0 += __shfl_xor_sync(0xffffffffu, a0, s);
            a1 += __shfl_xor_sync(0xffffffffu, a1, s);
            a2 += __shfl_xor_sync(0xffffffffu, a2, s);
            a3 += __shfl_xor_sync(0xffffffffu, a3, s);
        }

        float si = sigmoid_f(a0 + xg0);
        float sf = sigmoid_f(a1 + xg1);
        float tg = tanh_f   (a2 + xg2);
        float so = sigmoid_f(a3 + xg3);
        c = sf * c + si * tg;
        float h = so * tanh_f(c);

        xg0 = nx0; xg1 = nx1; xg2 = nx2; xg3 = nx3;

        if (t == SEQ - 1) {
            if (lane == 0) out[j] = h;
        } else if (lane == 0) {
            // aligned 8B store publishes value+tag together (R3-identical)
            __stcg(&g_hpair[(t + 1) & 1][j], make_float2(h, (float)(t + 1)));
        }
    }
}

// ---------------- launch -----------------------------------------------------
extern "C" void kernel_launch(void* const* d_in, const int* in_sizes, int n_in,
                              void* d_out, int out_size)
{
    const int*   x    = (const int*)  d_in[0];
    const float* emb  = (const float*)d_in[1];
    const float* W_ih = (const float*)d_in[2];
    const float* W_hh = (const float*)d_in[3];
    const float* b_ih = (const float*)d_in[4];
    const float* b_hh = (const float*)d_in[5];
    const float* h0   = (const float*)d_in[6];
    const float* c0   = (const float*)d_in[7];
    float* out = (float*)d_out;

    init_kernel<<<2, 256>>>(h0);
    dim3 g(SEQ / TT, G4 / TR);
    gemm_kernel<<<g, 256>>>(x, emb, W_ih, b_ih, b_hh);
    lstm_kernel<<<NCTA, NTHR>>>(W_hh, c0, out);
}

// round 12
// speedup vs baseline: 1.7778x; 1.7778x over previous
#include <cuda_runtime.h>
#include <cstdint>

#define SEQ   8192
#define EMB   256
#define HID   512
#define G4    2048   // 4*HID

// ---------------- scratch (static device arrays; no allocation) -------------
__device__ float g_Xg[(size_t)SEQ * G4];             // 64 MB precomputed input gates
__device__ __align__(16) float2 g_hpair[2][HID];     // (value, tag) pairs, 2 rotating slots

// ---------------- init: seed slot0 with (h0, tag=0), stamp slot1 ------------
__global__ void init_kernel(const float* __restrict__ h0) {
    int i = blockIdx.x * blockDim.x + threadIdx.x;
    if (i < HID) {
        g_hpair[0][i] = make_float2(h0[i], 0.0f);
        g_hpair[1][i] = make_float2(0.0f, -1.0f);   // never matches any expected tag
    }
}

// ---------------- GEMM: Xg[t][r] = emb[x[t]] . W_ih[r] + b_ih[r] + b_hh[r] --
#define TT 32
#define TR 64
#define KC 64

__global__ void __launch_bounds__(256) gemm_kernel(
    const int* __restrict__ x, const float* __restrict__ emb,
    const float* __restrict__ W_ih, const float* __restrict__ b_ih,
    const float* __restrict__ b_hh)
{
    __shared__ float As[TT][KC + 1];   // [t][k], padded
    __shared__ float Bs[KC][TR];       // [k][r]

    const int t0 = blockIdx.x * TT;
    const int r0 = blockIdx.y * TR;
    const int tid = threadIdx.x;
    const int tx = tid & 15;    // r-quad index (r = r0 + tx*4 + q)
    const int ty = tid >> 4;    // t index (t = t0 + ty, t0 + ty + 16)

    float acc[2][4];
    #pragma unroll
    for (int i = 0; i < 2; i++)
        #pragma unroll
        for (int q = 0; q < 4; q++) acc[i][q] = 0.f;

    for (int kc = 0; kc < EMB; kc += KC) {
        #pragma unroll
        for (int i = 0; i < 2; i++) {
            int task = tid * 2 + i;        // 0..511
            int t    = task >> 4;          // 16 float4 per row
            int kq   = task & 15;
            int row  = x[t0 + t];
            float4 v = *reinterpret_cast<const float4*>(
                emb + (size_t)row * EMB + kc + kq * 4);
            As[t][kq * 4 + 0] = v.x;
            As[t][kq * 4 + 1] = v.y;
            As[t][kq * 4 + 2] = v.z;
            As[t][kq * 4 + 3] = v.w;
        }
        #pragma unroll
        for (int i = 0; i < 4; i++) {
            int task = tid * 4 + i;        // 0..1023
            int r    = task >> 4;          // 0..63
            int kq   = task & 15;
            float4 v = *reinterpret_cast<const float4*>(
                W_ih + (size_t)(r0 + r) * EMB + kc + kq * 4);
            Bs[kq * 4 + 0][r] = v.x;
            Bs[kq * 4 + 1][r] = v.y;
            Bs[kq * 4 + 2][r] = v.z;
            Bs[kq * 4 + 3][r] = v.w;
        }
        __syncthreads();

        #pragma unroll 8
        for (int k = 0; k < KC; k++) {
            float a0 = As[ty][k];
            float a1 = As[ty + 16][k];
            float4 b = *reinterpret_cast<const float4*>(&Bs[k][tx * 4]);
            acc[0][0] += a0 * b.x;  acc[0][1] += a0 * b.y;
            acc[0][2] += a0 * b.z;  acc[0][3] += a0 * b.w;
            acc[1][0] += a1 * b.x;  acc[1][1] += a1 * b.y;
            acc[1][2] += a1 * b.z;  acc[1][3] += a1 * b.w;
        }
        __syncthreads();
    }

    const int rbase = r0 + tx * 4;
    float4 bias;
    bias.x = b_ih[rbase + 0] + b_hh[rbase + 0];
    bias.y = b_ih[rbase + 1] + b_hh[rbase + 1];
    bias.z = b_ih[rbase + 2] + b_hh[rbase + 2];
    bias.w = b_ih[rbase + 3] + b_hh[rbase + 3];
    #pragma unroll
    for (int i = 0; i < 2; i++) {
        int t = t0 + ty + i * 16;
        float4 o;
        o.x = acc[i][0] + bias.x;
        o.y = acc[i][1] + bias.y;
        o.z = acc[i][2] + bias.z;
        o.w = acc[i][3] + bias.w;
        *reinterpret_cast<float4*>(g_Xg + (size_t)t * G4 + rbase) = o;
    }
}

// ---------------- recurrent LSTM: persistent, collective-agree synced --------
#define NCTA   128
#define NWARP  4      // warps per CTA; NCTA*NWARP == HID (one unit per warp)
#define NTHR   (NWARP * 32)   // 128: one warp per SMSP — dedicated scheduler

__device__ __forceinline__ float sigmoid_f(float x) {
    return __fdividef(1.f, 1.f + __expf(-x));
}
__device__ __forceinline__ float tanh_f(float x) {
    float e = __expf(2.f * x);
    return 1.f - __fdividef(2.f, e + 1.f);
}

__device__ __forceinline__ unsigned long long pack2(float lo, float hi) {
    unsigned long long r;
    asm("mov.b64 %0, {%1, %2};" : "=l"(r)
        : "r"(__float_as_uint(lo)), "r"(__float_as_uint(hi)));
    return r;
}
__device__ __forceinline__ void unpack2(unsigned long long v, float& lo, float& hi) {
    unsigned a, b;
    asm("mov.b64 {%0, %1}, %2;" : "=r"(a), "=r"(b) : "l"(v));
    lo = __uint_as_float(a); hi = __uint_as_float(b);
}
__device__ __forceinline__ void ffma2(unsigned long long& acc,
                                      unsigned long long a, unsigned long long b) {
    asm("fma.rn.f32x2 %0, %1, %2, %0;" : "+l"(acc) : "l"(a), "l"(b));
}

__global__ void __launch_bounds__(NTHR, 1) lstm_kernel(
    const float* __restrict__ W_hh, const float* __restrict__ c0,
    float* __restrict__ out)
{
    const int tid  = threadIdx.x;
    const int warp = tid >> 5;
    const int lane = tid & 31;
    const int j = blockIdx.x * NWARP + warp;     // hidden unit 0..511

    // single-buffer staging is safe: the barrier INSIDE the poll loop means all
    // warps finished step-t matvec reads before anyone passes the step-(t+1)
    // poll and restages (R3 invariant).
    __shared__ __align__(16) float hsm[HID];

    // --- preload 4 gate rows of W_hh, packed (gate0,gate1)/(gate2,gate3).
    // lane l owns k in { q*128 + l*4 + e : q=0..3, e=0..3 }  (matches hsm layout)
    unsigned long long w01[16], w23[16];
    {
        float wt[4][16];
        #pragma unroll
        for (int g = 0; g < 4; g++) {
            const float* row = W_hh + (size_t)(g * HID + j) * HID;
            #pragma unroll
            for (int q = 0; q < 4; q++) {
                float4 v = *reinterpret_cast<const float4*>(row + q * 128 + lane * 4);
                wt[g][q * 4 + 0] = v.x; wt[g][q * 4 + 1] = v.y;
                wt[g][q * 4 + 2] = v.z; wt[g][q * 4 + 3] = v.w;
            }
        }
        #pragma unroll
        for (int k = 0; k < 16; k++) {
            w01[k] = pack2(wt[0][k], wt[1][k]);
            w23[k] = pack2(wt[2][k], wt[3][k]);
        }
    }

    float c = c0[j];

    // prefetch Xg for t=0 (broadcast per warp)
    float xg0 = g_Xg[j +    0];
    float xg1 = g_Xg[j +  512];
    float xg2 = g_Xg[j + 1024];
    float xg3 = g_Xg[j + 1536];

    for (int t = 0; t < SEQ; t++) {
        // prefetch next step's Xg FIRST — latency hides under the poll
        int tn = (t + 1 < SEQ) ? (t + 1) : t;
        const float* xpn = g_Xg + (size_t)tn * G4 + j;
        float nx0 = xpn[0], nx1 = xpn[512], nx2 = xpn[1024], nx3 = xpn[1536];

        // ---- CTA-collective poll (R3-exact): 4 pairs/thread via 2x LDG.128,
        // all 128 threads agree via __syncthreads_and before anyone proceeds.
        const float4* src = reinterpret_cast<const float4*>(g_hpair[t & 1]);
        const int exp_bits = __float_as_int((float)t);
        float4 pa, pb;
        int ok;
        do {
            pa = __ldcv(src + tid * 2 + 0);   // pairs 4*tid, 4*tid+1
            pb = __ldcv(src + tid * 2 + 1);   // pairs 4*tid+2, 4*tid+3
            ok = (__float_as_int(pa.y) == exp_bits) &
                 (__float_as_int(pa.w) == exp_bits) &
                 (__float_as_int(pb.y) == exp_bits) &
                 (__float_as_int(pb.w) == exp_bits);
        } while (!__syncthreads_and(ok));

        // stage values to smem (one STS.128 per thread), visibility barrier
        *reinterpret_cast<float4*>(&hsm[tid * 4]) =
            make_float4(pa.x, pa.z, pb.x, pb.z);
        __syncthreads();

        // matvec slice: packed f32x2 — (gate0,gate1) and (gate2,gate3) pairs
        unsigned long long A01 = 0ull, A23 = 0ull;   // bit pattern (0.0f, 0.0f)
        #pragma unroll
        for (int q = 0; q < 4; q++) {
            float4 hq = *reinterpret_cast<const float4*>(&hsm[q * 128 + lane * 4]);
            float hv[4] = {hq.x, hq.y, hq.z, hq.w};
            #pragma unroll
            for (int e = 0; e < 4; e++) {
                unsigned long long hh = pack2(hv[e], hv[e]);
                ffma2(A01, w01[q * 4 + e], hh);
                ffma2(A23, w23[q * 4 + e], hh);
            }
        }
        float a0, a1, a2, a3;
        unpack2(A01, a0, a1);
        unpack2(A23, a2, a3);
        #pragma unroll
        for (int s = 16; s > 0; s >>= 1) {
            a0 += __shfl_xor_sync(0xffffffffu, a0, s);
            a1 += __shfl_xor_sync(0xffffffffu, a1, s);
            a2 += __shfl_xor_sync(0xffffffffu, a2, s);
            a3 += __shfl_xor_sync(0xffffffffu, a3, s);
        }

        float si = sigmoid_f(a0 + xg0);
        float sf = sigmoid_f(a1 + xg1);
        float tg = tanh_f   (a2 + xg2);
        float so = sigmoid_f(a3 + xg3);
        c = sf * c + si * tg;
        float h = so * tanh_f(c);

        xg0 = nx0; xg1 = nx1; xg2 = nx2; xg3 = nx3;

        if (t == SEQ - 1) {
            if (lane == 0) out[j] = h;
        } else if (lane == 0) {
            // aligned 8B store publishes value+tag together (R3-identical)
            __stcg(&g_hpair[(t + 1) & 1][j], make_float2(h, (float)(t + 1)));
        }
    }
}

// ---------------- launch -----------------------------------------------------
extern "C" void kernel_launch(void* const* d_in, const int* in_sizes, int n_in,
                              void* d_out, int out_size)
{
    const int*   x    = (const int*)  d_in[0];
    const float* emb  = (const float*)d_in[1];
    const float* W_ih = (const float*)d_in[2];
    const float* W_hh = (const float*)d_in[3];
    const float* b_ih = (const float*)d_in[4];
    const float* b_hh = (const float*)d_in[5];
    const float* h0   = (const float*)d_in[6];
    const float* c0   = (const float*)d_in[7];
    float* out = (float*)d_out;

    init_kernel<<<2, 256>>>(h0);
    dim3 g(SEQ / TT, G4 / TR);
    gemm_kernel<<<g, 256>>>(x, emb, W_ih, b_ih, b_hh);
    lstm_kernel<<<NCTA, NTHR>>>(W_hh, c0, out);
}